// round 14
// baseline (speedup 1.0000x reference)
#include <cuda_runtime.h>

// LSTM scan: T=2048, B=2048, IN=5, H=10.
// R9 = R8 datapath (365us), geometry 2-warp -> 4-warp blocks.
//   R8's 2-warp blocks put 2.3 warps on each of ONLY 2 SMSPs: per-active-SMSP
//   fma pipe ~51% -> fma-issue pressure (~207 SMSP-cyc/step) rivals the chain.
//   4-warp blocks spread 683 warps over all 4 SMSPs (1.15/SMSP): fma pressure
//   halves. R4's failure at this geometry came from its per-step branch +
//   10-SHFL exchange, both long gone.
//   Micro: chain-critical LDS issued before the prefetch LDGs (LSU order).
// Datapath kept: sync-free smem h double-buffer (2x LDS.128 + LDS.64, 64B
// rows), PF=4 raw-x ring, prescaled i/f/o weights, 3+2 split h-dot + fadd2,
// pre-packed bias, STS before STG, MUFU.TANH, f32x2 gate math.

#define T_STEPS 2048
#define BATCH   2048
#define IN_DIM  5
#define HID     10
#define BPW     3                               // batches per warp (30 lanes)
#define WARPS   4
#define NTHREADS (WARPS * 32)                   // 128
#define BPB     (WARPS * BPW)                   // 12 batches per block
#define NBLOCKS ((BATCH + BPB - 1) / BPB)       // 171
#define PF      4                               // x prefetch depth (divides T)

typedef unsigned long long u64;

__device__ __forceinline__ u64 pack2(float lo, float hi) {
    u64 r;
    asm("mov.b64 %0, {%1, %2};" : "=l"(r) : "f"(lo), "f"(hi));
    return r;
}
__device__ __forceinline__ void unpack2(u64 v, float& lo, float& hi) {
    asm("mov.b64 {%0, %1}, %2;" : "=f"(lo), "=f"(hi) : "l"(v));
}
__device__ __forceinline__ u64 ffma2(u64 a, u64 b, u64 c) {
    u64 d;
    asm("fma.rn.f32x2 %0, %1, %2, %3;" : "=l"(d) : "l"(a), "l"(b), "l"(c));
    return d;
}
__device__ __forceinline__ u64 fmul2(u64 a, u64 b) {
    u64 d;
    asm("mul.rn.f32x2 %0, %1, %2;" : "=l"(d) : "l"(a), "l"(b));
    return d;
}
__device__ __forceinline__ u64 fadd2(u64 a, u64 b) {
    u64 d;
    asm("add.rn.f32x2 %0, %1, %2;" : "=l"(d) : "l"(a), "l"(b));
    return d;
}
__device__ __forceinline__ float tanha(float z) {
    float r;
    asm("tanh.approx.f32 %0, %1;" : "=f"(r) : "f"(z));
    return r;
}
// weights already prescaled by 0.5 for sigmoid gates:
__device__ __forceinline__ float fsig_pre(float zh) {   // zh = 0.5*z
    return fmaf(0.5f, tanha(zh), 0.5f);
}

// One LSTM step. DOPF: issue the x prefetch for PF steps ahead.
// par = d&1 selects the h double-buffer (compile-time after unroll).
// No syncwarp: converged warp; STS(t) -> LDS(t+1) is per-warp program-
// ordered through the LSU. LDS issued FIRST so the chain-critical load
// enters the LSU ahead of the slack-rich prefetch LDGs.
#define STEP_BODY(d, DOPF) do {                                               \
    const int par_ = (d) & 1;                                                 \
    /* chain head: previous step's h, 2x LDS.128 + 1x LDS.64 */               \
    const float4 hA = *rpA[par_];                                             \
    const float4 hB = *rpB[par_];                                             \
    const float2 hC = *rpC[par_];                                             \
    float nx0, nx1, nx2, nx3, nx4;                                            \
    if (DOPF) {                       /* compile-time constant */             \
        nx0 = __ldg(xpf + 0); nx1 = __ldg(xpf + 1); nx2 = __ldg(xpf + 2);     \
        nx3 = __ldg(xpf + 3); nx4 = __ldg(xpf + 4);                           \
        xpf += xstep;                                                         \
    }                                                                         \
    const u64 hp0 = pack2(hA.x, hA.y), hp1 = pack2(hA.z, hA.w);               \
    const u64 hp2 = pack2(hB.x, hB.y), hp3 = pack2(hB.z, hB.w);               \
    const u64 hp4 = pack2(hC.x, hC.y);                                        \
    const u64 v0 = pack2(xr[d][0], xr[d][1]);                                 \
    const u64 v1 = pack2(xr[d][2], xr[d][3]);                                 \
    const u64 v2 = pack2(xr[d][4], 0.0f);                                     \
    float gate[4];                                                            \
    _Pragma("unroll")                                                         \
    for (int q = 0; q < 4; q++) {                                             \
        u64 accA = biasp[q];          /* x-part retires during LDS wait */    \
        accA = ffma2(wp[q][0], v0, accA);                                     \
        accA = ffma2(wp[q][1], v1, accA);                                     \
        accA = ffma2(wp[q][2], v2, accA);                                     \
        accA = ffma2(wp[q][3], hp0, accA);                                    \
        accA = ffma2(wp[q][4], hp1, accA);                                    \
        accA = ffma2(wp[q][5], hp2, accA);                                    \
        u64 accB = fmul2(wp[q][6], hp3);   /* parallel 2-chain */             \
        accB = ffma2(wp[q][7], hp4, accB);                                    \
        const u64 acc = fadd2(accA, accB);                                    \
        float lo_, hi_; unpack2(acc, lo_, hi_);                               \
        gate[q] = lo_ + hi_;                                                  \
    }                                                                         \
    const float is = fsig_pre(gate[0]);                                       \
    const float fs = fsig_pre(gate[1]);                                       \
    const float gt = tanha(gate[2]);                                          \
    const float os = fsig_pre(gate[3]);                                       \
    c = fs * c + is * gt;                                                     \
    const float hn = os * tanha(c);                                           \
    wq[par_ ^ 1][0] = hn;             /* STS first: feeds next step's chain */\
    if (active) *op = hn;             /* STG after: fire-and-forget */        \
    op += ostep;                                                              \
    if (DOPF) {                                                               \
        xr[d][0] = nx0; xr[d][1] = nx1; xr[d][2] = nx2;                       \
        xr[d][3] = nx3; xr[d][4] = nx4;                                       \
    }                                                                         \
} while (0)

__global__ void __launch_bounds__(NTHREADS, 1) lstm_scan_kernel(
    const float* __restrict__ x,     // [T, B, IN]
    const float* __restrict__ hx0,   // [B, H]
    const float* __restrict__ cx0,   // [B, H]
    const float* __restrict__ Wih,   // [4H, IN]
    const float* __restrict__ Whh,   // [4H, H]
    const float* __restrict__ bih,   // [4H]
    const float* __restrict__ bhh,   // [4H]
    float* __restrict__ out)         // [T*B, H]
{
    // Double-buffered h, per warp. Group rows padded to 16 floats (64B):
    // rows 16B-aligned -> LDS.128 legal. Row 3 = scratch for the two
    // inactive lanes (written, never read). Within a group all lanes read
    // the same 16B line (broadcast); groups hit disjoint lines: no
    // conflicts.
    __shared__ __align__(16) float hbuf[2][WARPS][4][16];

    const int lane = threadIdx.x & 31;
    const int warp = threadIdx.x >> 5;
    const int g    = lane / HID;          // batch slot in warp (0..3)
    const int h    = lane % HID;          // hidden unit 0..9

    const int  b_raw  = blockIdx.x * BPB + warp * BPW + g;
    const bool active = (g < BPW) && (b_raw < BATCH);
    const int  b      = active ? b_raw : (BATCH - 1);   // clamp: safe loads

    // Pack weights, v-layout [x0..x4, 0, h0..h9] (8 f32x2 per gate).
    // Gates i,f,o (q != 2) prescaled by 0.5 -> sigmoid needs no pre-mul.
    u64 wp[4][8];
    u64 biasp[4];
#pragma unroll
    for (int q = 0; q < 4; q++) {
        const float sc = (q == 2) ? 1.0f : 0.5f;
        const int r = q * HID + h;
        float wv[16];
#pragma unroll
        for (int k = 0; k < IN_DIM; k++) wv[k] = sc * Wih[r * IN_DIM + k];
        wv[5] = 0.0f;                                    // pad slot
#pragma unroll
        for (int j = 0; j < HID; j++) wv[6 + j] = sc * Whh[r * HID + j];
#pragma unroll
        for (int p = 0; p < 8; p++) wp[q][p] = pack2(wv[2 * p], wv[2 * p + 1]);
        biasp[q] = pack2(sc * (bih[r] + bhh[r]), 0.0f);
    }

    float c = cx0[(size_t)b * HID + h];

    // h exchange pointers (computed once). Reads use the group row clamped
    // to a valid group; inactive lanes write into scratch row 3.
    const int gr = (g < BPW) ? g : (BPW - 1);
    const float4* rpA[2] = { (const float4*)&hbuf[0][warp][gr][0],
                             (const float4*)&hbuf[1][warp][gr][0] };
    const float4* rpB[2] = { (const float4*)&hbuf[0][warp][gr][4],
                             (const float4*)&hbuf[1][warp][gr][4] };
    const float2* rpC[2] = { (const float2*)&hbuf[0][warp][gr][8],
                             (const float2*)&hbuf[1][warp][gr][8] };
    float* wq[2] = { &hbuf[0][warp][g][h],
                     &hbuf[1][warp][g][h] };
    wq[0][0] = hx0[(size_t)b * HID + h];   // initial h into buffer 0
    __syncwarp();                          // one-time: order init vs step 0

    // Preload x rows 0..PF-1 into the register ring.
    float xr[PF][IN_DIM];
#pragma unroll
    for (int d = 0; d < PF; d++) {
        const float* pp = x + ((size_t)d * BATCH + b) * IN_DIM;
#pragma unroll
        for (int k = 0; k < IN_DIM; k++) xr[d][k] = __ldg(pp + k);
    }

    const size_t xstep = (size_t)BATCH * IN_DIM;
    const size_t ostep = (size_t)BATCH * HID;
    const float* xpf = x + ((size_t)PF * BATCH + b) * IN_DIM;   // next fetch
    float* op = out + (size_t)b * HID + h;

    // Main loop: all chunks except the last prefetch unconditionally.
#pragma unroll 1
    for (int tc = 0; tc < T_STEPS - PF; tc += PF) {
#pragma unroll
        for (int d = 0; d < PF; d++) STEP_BODY(d, true);
    }
    // Peeled final chunk: consume the ring, no prefetch, no branches.
#pragma unroll
    for (int d = 0; d < PF; d++) STEP_BODY(d, false);
}

extern "C" void kernel_launch(void* const* d_in, const int* in_sizes, int n_in,
                              void* d_out, int out_size) {
    (void)in_sizes; (void)n_in; (void)out_size;
    const float* x   = (const float*)d_in[0];
    const float* hx0 = (const float*)d_in[1];
    const float* cx0 = (const float*)d_in[2];
    const float* Wih = (const float*)d_in[3];
    const float* Whh = (const float*)d_in[4];
    const float* bih = (const float*)d_in[5];
    const float* bhh = (const float*)d_in[6];
    float* out = (float*)d_out;

    lstm_scan_kernel<<<NBLOCKS, NTHREADS>>>(x, hx0, cx0, Wih, Whh, bih, bhh, out);
}